// round 15
// baseline (speedup 1.0000x reference)
#include <cuda_runtime.h>
#include <cuda_bf16.h>
#include <cstdint>

// ---------------- problem-size constants (fixed by the dataset) -------------
#define MAXN 100000
#define MAXE 1600000

// ---------------- device scratch (allocation-free rule: __device__ globals) -
__device__ __align__(16) float g_Y [MAXN * 256];   // [y1 | y2 | y0 | pad], stride 256
__device__ __align__(16) float g_U [MAXN * 64];    // u = y1 + 2*L y2
__device__ __align__(16) float g_H2[MAXN * 192];   // [h1 | t1 | t2] for layer 2
__device__ __align__(16) float g_H3[MAXN * 384];   // [h2 | t1 | t2] for layer 3
__device__ __align__(16) float g_Wcat[128 * 256];  // [W1_1 | W1_2 | W1_0-W1_2 | 0]

// B weights pre-packed in mma-fragment order:
// one uint4 per (n8-tile, k16-chunk, lane) = {b0_hi, b1_hi, b0_lo, b1_lo}
// where b0 = bf16 pair at k=2q(+1), b1 = pair at k=2q+8(+1), n = tile*8 + g.
// GEMM1: base 0     (32 tiles x  8 k16 x 32 = 8192)
// GEMM2: base 8192  (16 tiles x 12 k16 x 32 = 6144)
// GEMM3: base 14336 (32 tiles x 24 k16 x 32 = 24576)
#define BP_TOTAL 38912
__device__ __align__(16) uint4 g_Bp[BP_TOTAL];

__device__ float g_dinv[MAXN];
__device__ int   g_deg [MAXN];
__device__ int   g_cnt [MAXN];
__device__ int   g_cur [MAXN];
__device__ int   g_rowstart[MAXN];
__device__ int   g_blocksums[256];
__device__ int   g_csr_src[MAXE];
__device__ float g_csr_w [MAXE];
__device__ int   g_is64;          // 1 if edge_index is int64, 0 if int32

// ---------------- PTX helpers (baseline sm_80+ features only) ----------------
__device__ __forceinline__ void mma_bf16(float* c, const uint32_t* a,
                                         uint32_t b0, uint32_t b1) {
    asm volatile(
        "mma.sync.aligned.m16n8k16.row.col.f32.bf16.bf16.f32 "
        "{%0,%1,%2,%3}, {%4,%5,%6,%7}, {%8,%9}, {%0,%1,%2,%3};"
        : "+f"(c[0]), "+f"(c[1]), "+f"(c[2]), "+f"(c[3])
        : "r"(a[0]), "r"(a[1]), "r"(a[2]), "r"(a[3]), "r"(b0), "r"(b1));
}
__device__ __forceinline__ uint32_t bf2u(__nv_bfloat16 a, __nv_bfloat16 b) {
    __nv_bfloat162 p = __halves2bfloat162(a, b);
    return *reinterpret_cast<uint32_t*>(&p);
}

// ---------------- edge dtype detection + access -----------------------------
__device__ __forceinline__ void load_edge(const void* ei, int e, int E, int is64,
                                          int& s, int& d) {
    if (is64) {
        const long long* p = (const long long*)ei;
        s = (int)p[e];
        d = (int)p[E + e];
    } else {
        const int* p = (const int*)ei;
        s = p[e];
        d = p[E + e];
    }
}

// ---------------- setup kernels ---------------------------------------------
__global__ void init_kernel(const int* __restrict__ ei32, int E, int N) {
    int i = blockIdx.x * blockDim.x + threadIdx.x;
    if (i < N) { g_deg[i] = 0; g_cnt[i] = 0; g_cur[i] = 0; }
    if (i == 0) {
        int is64 = 1;
        int nchk = (E < 64) ? E : 64;
        for (int j = 0; j < nchk; j++) {
            if (ei32[2 * j + 1] != 0) { is64 = 0; break; }
        }
        g_is64 = is64;
    }
}

__global__ void deg_cnt_kernel(const void* __restrict__ ei, int E) {
    int e = blockIdx.x * blockDim.x + threadIdx.x;
    if (e >= E) return;
    int is64 = g_is64;
    int s, d;
    load_edge(ei, e, E, is64, s, d);
    if (s != d) {
        atomicAdd(&g_deg[s], 1);
        atomicAdd(&g_cnt[d], 1);
    }
}

__global__ void scan1_kernel(int N) {
    __shared__ int sm[1024];
    int t = threadIdx.x;
    int i = blockIdx.x * 1024 + t;
    if (i < N) {
        int dg = g_deg[i];
        g_dinv[i] = (dg > 0) ? rsqrtf((float)dg) : 0.0f;
    }
    int v = (i < N) ? g_cnt[i] : 0;
    sm[t] = v;
    __syncthreads();
    for (int off = 1; off < 1024; off <<= 1) {
        int x = (t >= off) ? sm[t - off] : 0;
        __syncthreads();
        sm[t] += x;
        __syncthreads();
    }
    if (i < N) g_rowstart[i] = sm[t] - v;
    if (t == 1023) g_blocksums[blockIdx.x] = sm[1023];
}

__global__ void scan2_kernel(int nb) {
    __shared__ int sm[256];
    int t = threadIdx.x;
    int v = (t < nb) ? g_blocksums[t] : 0;
    sm[t] = v;
    __syncthreads();
    for (int off = 1; off < 256; off <<= 1) {
        int x = (t >= off) ? sm[t - off] : 0;
        __syncthreads();
        sm[t] += x;
        __syncthreads();
    }
    if (t < nb) g_blocksums[t] = sm[t] - v;
}

__global__ void scan3_kernel(int N) {
    int i = blockIdx.x * 1024 + threadIdx.x;
    if (i < N) g_rowstart[i] += g_blocksums[blockIdx.x];
}

__global__ void fill_kernel(const void* __restrict__ ei, int E) {
    int e = blockIdx.x * blockDim.x + threadIdx.x;
    if (e >= E) return;
    int is64 = g_is64;
    int s, d;
    load_edge(ei, e, E, is64, s, d);
    if (s != d) {
        float w = -g_dinv[s] * g_dinv[d];
        int p = g_rowstart[d] + atomicAdd(&g_cur[d], 1);
        g_csr_src[p] = s;
        g_csr_w[p]   = w;
    }
}

// Wcat = [W1[1] | W1[2] | W1[0]-W1[2] | zeros]   (128 x 256)
__global__ void wcat_kernel(const float* __restrict__ W1, float* __restrict__ Wc) {
    int idx = blockIdx.x * blockDim.x + threadIdx.x;
    if (idx >= 128 * 256) return;
    int i = idx / 256, j = idx % 256;
    float v;
    if (j < 64)        v = W1[8192     + i * 64 + j];
    else if (j < 128)  v = W1[2 * 8192 + i * 64 + (j - 64)];
    else if (j < 192)  v = W1[           i * 64 + (j - 128)]
                         - W1[2 * 8192 + i * 64 + (j - 128)];
    else               v = 0.f;
    Wc[idx] = v;
}

// Weight prep: fp32 W[K,N] -> fragment-packed bf16 hi/lo uint4 per lane.
__global__ void wprep_all(const float* __restrict__ Wc,
                          const float* __restrict__ W2,
                          const float* __restrict__ W3) {
    int idx = blockIdx.x * blockDim.x + threadIdx.x;
    if (idx >= BP_TOTAL) return;
    const float* W; int ldw, nk16, local;
    if (idx < 8192)        { W = Wc; ldw = 256; nk16 = 8;  local = idx; }
    else if (idx < 14336)  { W = W2; ldw = 128; nk16 = 12; local = idx - 8192; }
    else                   { W = W3; ldw = 256; nk16 = 24; local = idx - 14336; }
    int per_tile = nk16 * 32;
    int t   = local / per_tile;
    int rem = local % per_tile;
    int c   = rem >> 5;
    int l   = rem & 31;
    int g = l >> 2, q = l & 3;
    int n  = t * 8 + g;
    int k0 = c * 16 + 2 * q;
    float v00 = W[(size_t)(k0    ) * ldw + n];
    float v01 = W[(size_t)(k0 + 1) * ldw + n];
    float v10 = W[(size_t)(k0 + 8) * ldw + n];
    float v11 = W[(size_t)(k0 + 9) * ldw + n];
    __nv_bfloat16 h00 = __float2bfloat16(v00);
    __nv_bfloat16 h01 = __float2bfloat16(v01);
    __nv_bfloat16 h10 = __float2bfloat16(v10);
    __nv_bfloat16 h11 = __float2bfloat16(v11);
    __nv_bfloat16 l00 = __float2bfloat16(v00 - __bfloat162float(h00));
    __nv_bfloat16 l01 = __float2bfloat16(v01 - __bfloat162float(h01));
    __nv_bfloat16 l10 = __float2bfloat16(v10 - __bfloat162float(h10));
    __nv_bfloat16 l11 = __float2bfloat16(v11 - __bfloat162float(h11));
    uint4 o;
    o.x = bf2u(h00, h01);
    o.y = bf2u(h10, h11);
    o.z = bf2u(l00, l01);
    o.w = bf2u(l10, l11);
    g_Bp[idx] = o;
}

// ---------------- fragment-direct mma.sync GEMM (ZERO shared memory) --------
// C = A @ W (+bias)(+relu); bf16x3 split AhBh + AhBl + AlBh, fp32 accum.
// CTA 128x128, 8 warps (4m x 2n), warp tile 32x64.
// A fragments LDG'd directly per lane (m16n8k16 row layout); B fragments
// pre-packed (wprep_all) and fetched as one coalesced LDG.128 per lane.
// No smem, no __syncthreads; register double-buffered over k16 chunks.
// Requires K % 32 == 0 (nk16 even), N % 128 == 0 for B pack.
__global__ __launch_bounds__(256) void mma_gemm(
    const float* __restrict__ A, int lda, int nk16,
    const uint4* __restrict__ Bp,
    float* __restrict__ C, int ldc, int M,
    const float* __restrict__ bias, int do_relu)
{
    int tid = threadIdx.x, lane = tid & 31, wid = tid >> 5;
    int m0 = blockIdx.y * 128, n0 = blockIdx.x * 128;
    int wm = (wid >> 1) * 32, wn = (wid & 1) * 64;
    int g = lane >> 2, q = lane & 3;

    float acc[2][8][4];
#pragma unroll
    for (int i = 0; i < 2; i++)
#pragma unroll
        for (int j = 0; j < 8; j++)
#pragma unroll
            for (int r = 0; r < 4; r++) acc[i][j][r] = 0.f;

    // A fragment row pointers (row g of each m16 tile; +8*lda for row g+8)
    const float* pa0[2];
    bool v0[2], v1[2];
#pragma unroll
    for (int mt = 0; mt < 2; mt++) {
        int r0 = m0 + wm + mt * 16 + g;
        v0[mt] = r0 < M;
        v1[mt] = (r0 + 8) < M;
        pa0[mt] = A + (size_t)r0 * lda + 2 * q;
    }
    const size_t row8 = (size_t)8 * lda;

    // B fragment pointer: tile stride = nk16*32 uint4
    const uint4* bp0 = Bp + (size_t)((n0 + wn) >> 3) * nk16 * 32 + lane;
    const int bstr = nk16 * 32;

#define LOADA(dst, c) do {                                                     \
    int off_ = (c) * 16;                                                       \
    _Pragma("unroll")                                                          \
    for (int mt_ = 0; mt_ < 2; mt_++) {                                        \
        dst[mt_][0] = v0[mt_] ? *(const float2*)(pa0[mt_] + off_)              \
                              : make_float2(0.f, 0.f);                         \
        dst[mt_][1] = v1[mt_] ? *(const float2*)(pa0[mt_] + row8 + off_)       \
                              : make_float2(0.f, 0.f);                         \
        dst[mt_][2] = v0[mt_] ? *(const float2*)(pa0[mt_] + off_ + 8)          \
                              : make_float2(0.f, 0.f);                         \
        dst[mt_][3] = v1[mt_] ? *(const float2*)(pa0[mt_] + row8 + off_ + 8)   \
                              : make_float2(0.f, 0.f);                         \
    } } while (0)

#define LOADB(dst, c) do {                                                     \
    int c32_ = (c) * 32;                                                       \
    _Pragma("unroll")                                                          \
    for (int nt_ = 0; nt_ < 8; nt_++)                                          \
        dst[nt_] = bp0[nt_ * bstr + c32_];                                     \
    } while (0)

#define DOMMA(aset, bset) do {                                                 \
    uint32_t ah_[2][4], al_[2][4];                                             \
    _Pragma("unroll")                                                          \
    for (int mt_ = 0; mt_ < 2; mt_++) {                                        \
        _Pragma("unroll")                                                      \
        for (int i_ = 0; i_ < 4; i_++) {                                       \
            float x_ = aset[mt_][i_].x, y_ = aset[mt_][i_].y;                  \
            __nv_bfloat16 hx_ = __float2bfloat16(x_);                          \
            __nv_bfloat16 hy_ = __float2bfloat16(y_);                          \
            ah_[mt_][i_] = bf2u(hx_, hy_);                                     \
            al_[mt_][i_] = bf2u(__float2bfloat16(x_ - __bfloat162float(hx_)),  \
                                __float2bfloat16(y_ - __bfloat162float(hy_)));  \
        }                                                                      \
    }                                                                          \
    _Pragma("unroll")                                                          \
    for (int nt_ = 0; nt_ < 8; nt_++) {                                        \
        uint4 b_ = bset[nt_];                                                  \
        _Pragma("unroll")                                                      \
        for (int mt_ = 0; mt_ < 2; mt_++) {                                    \
            mma_bf16(acc[mt_][nt_], ah_[mt_], b_.x, b_.y);                     \
            mma_bf16(acc[mt_][nt_], ah_[mt_], b_.z, b_.w);                     \
            mma_bf16(acc[mt_][nt_], al_[mt_], b_.x, b_.y);                     \
        }                                                                      \
    } } while (0)

    float2 aA[2][4], aB[2][4];
    uint4  bA[8],   bB[8];

    LOADA(aA, 0);
    LOADB(bA, 0);
    for (int c = 0; c < nk16; c += 2) {
        LOADA(aB, c + 1);
        LOADB(bB, c + 1);
        DOMMA(aA, bA);
        if (c + 2 < nk16) {
            LOADA(aA, c + 2);
            LOADB(bA, c + 2);
        }
        DOMMA(aB, bB);
    }

    // ---- epilogue: regs -> global with bias/relu ----
#pragma unroll
    for (int nt = 0; nt < 8; nt++) {
        int c = n0 + wn + nt * 8 + q * 2;
        float b0 = bias ? bias[c]     : 0.f;
        float b1 = bias ? bias[c + 1] : 0.f;
#pragma unroll
        for (int mt = 0; mt < 2; mt++) {
            int r0 = m0 + wm + mt * 16 + g;
            int r1 = r0 + 8;
            float* a4 = acc[mt][nt];
            float2 lo = make_float2(a4[0] + b0, a4[1] + b1);
            float2 hi = make_float2(a4[2] + b0, a4[3] + b1);
            if (do_relu) {
                lo.x = fmaxf(lo.x, 0.f); lo.y = fmaxf(lo.y, 0.f);
                hi.x = fmaxf(hi.x, 0.f); hi.y = fmaxf(hi.y, 0.f);
            }
            if (r0 < M)
                *reinterpret_cast<float2*>(C + (size_t)r0 * ldc + c) = lo;
            if (r1 < M)
                *reinterpret_cast<float2*>(C + (size_t)r1 * ldc + c) = hi;
        }
    }
}

// ---------------- propagation: out = alpha*(L @ in) + beta*add + bias, relu -
__device__ __forceinline__ void accum4(float* acc, const float* p, float w) {
    float4 r = *reinterpret_cast<const float4*>(p);
    acc[0] = fmaf(w, r.x, acc[0]);
    acc[1] = fmaf(w, r.y, acc[1]);
    acc[2] = fmaf(w, r.z, acc[2]);
    acc[3] = fmaf(w, r.w, acc[3]);
}
__device__ __forceinline__ void accum2(float* acc, const float* p, float w) {
    float2 r = *reinterpret_cast<const float2*>(p);
    acc[0] = fmaf(w, r.x, acc[0]);
    acc[1] = fmaf(w, r.y, acc[1]);
}

template <int C>
__global__ __launch_bounds__(256) void prop_kernel(
    const float* __restrict__ in, int in_stride,
    float* __restrict__ out, int out_stride,
    const float* __restrict__ add, int add_stride,
    float alpha, float beta,
    const float* __restrict__ bias, int do_relu, int Nn)
{
    constexpr int V = C / 32;
    int gw = (blockIdx.x * blockDim.x + threadIdx.x) >> 5;
    int lane = threadIdx.x & 31;
    if (gw >= Nn) return;

    int start = g_rowstart[gw];
    int cnt = g_cnt[gw];
    float acc[V];
#pragma unroll
    for (int v = 0; v < V; v++) acc[v] = 0.f;

    const int feat = lane * V;
    int e = 0;
    for (; e + 4 <= cnt; e += 4) {
        int s0 = g_csr_src[start + e + 0];
        int s1 = g_csr_src[start + e + 1];
        int s2 = g_csr_src[start + e + 2];
        int s3 = g_csr_src[start + e + 3];
        float w0 = g_csr_w[start + e + 0];
        float w1 = g_csr_w[start + e + 1];
        float w2 = g_csr_w[start + e + 2];
        float w3 = g_csr_w[start + e + 3];
        const float* p0 = in + (size_t)s0 * in_stride + feat;
        const float* p1 = in + (size_t)s1 * in_stride + feat;
        const float* p2 = in + (size_t)s2 * in_stride + feat;
        const float* p3 = in + (size_t)s3 * in_stride + feat;
        if (V == 4) {
            accum4(acc, p0, w0); accum4(acc, p1, w1);
            accum4(acc, p2, w2); accum4(acc, p3, w3);
        } else {
            accum2(acc, p0, w0); accum2(acc, p1, w1);
            accum2(acc, p2, w2); accum2(acc, p3, w3);
        }
    }
    for (; e < cnt; e++) {
        int s = g_csr_src[start + e];
        float w = g_csr_w[start + e];
        const float* p = in + (size_t)s * in_stride + feat;
        if (V == 4) accum4(acc, p, w);
        else        accum2(acc, p, w);
    }

    float res[V];
#pragma unroll
    for (int v = 0; v < V; v++) res[v] = alpha * acc[v];
    if (add) {
        const float* ap = add + (size_t)gw * add_stride + feat;
        if (V == 4) {
            float4 a = *reinterpret_cast<const float4*>(ap);
            res[0] = fmaf(beta, a.x, res[0]);
            res[1] = fmaf(beta, a.y, res[1]);
            res[2] = fmaf(beta, a.z, res[2]);
            res[3] = fmaf(beta, a.w, res[3]);
        } else {
            float2 a = *reinterpret_cast<const float2*>(ap);
            res[0] = fmaf(beta, a.x, res[0]);
            res[1] = fmaf(beta, a.y, res[1]);
        }
    }
    if (bias) {
#pragma unroll
        for (int v = 0; v < V; v++) res[v] += bias[feat + v];
    }
    if (do_relu) {
#pragma unroll
        for (int v = 0; v < V; v++) res[v] = fmaxf(res[v], 0.f);
    }
    float* op = out + (size_t)gw * out_stride + feat;
    if (V == 4) {
        *reinterpret_cast<float4*>(op) = make_float4(res[0], res[1], res[2], res[3]);
    } else {
        *reinterpret_cast<float2*>(op) = make_float2(res[0], res[1]);
    }
}

// ---------------- launch ----------------------------------------------------
extern "C" void kernel_launch(void* const* d_in, const int* in_sizes, int n_in,
                              void* d_out, int out_size)
{
    const float* x  = (const float*)d_in[0];
    const void*  ei = d_in[1];
    const float* W1 = (const float*)d_in[3];
    const float* b1 = (const float*)d_in[4];
    const float* W2 = (const float*)d_in[5];
    const float* b2 = (const float*)d_in[6];
    const float* W3 = (const float*)d_in[7];
    const float* b3 = (const float*)d_in[8];

    int N = in_sizes[2];      // batch vector has N entries
    int E = in_sizes[1] / 2;

    float *Y, *U, *H2, *H3, *Wc;
    uint4 *Bp;
    cudaGetSymbolAddress((void**)&Y,  g_Y);
    cudaGetSymbolAddress((void**)&U,  g_U);
    cudaGetSymbolAddress((void**)&H2, g_H2);
    cudaGetSymbolAddress((void**)&H3, g_H3);
    cudaGetSymbolAddress((void**)&Wc, g_Wcat);
    cudaGetSymbolAddress((void**)&Bp, g_Bp);

    int nblk = (N + 255) / 256;
    int eblk = (E + 255) / 256;
    int nb1024 = (N + 1023) / 1024;
    int pblk = (N + 7) / 8;   // 8 warps / block
    int mgrid = (N + 127) / 128;

    // 1-3: setup + weight prep (GEMM1 lands in profiled slot 4)
    init_kernel<<<nblk, 256>>>((const int*)ei, E, N);
    wcat_kernel<<<(128 * 256 + 255) / 256, 256>>>(W1, Wc);
    wprep_all<<<(BP_TOTAL + 255) / 256, 256>>>(Wc, W2, W3);

    // 4: GEMM1 — Y[:,0:256] = x @ Wcat (fragment-direct tensor GEMM)
    {
        dim3 g(2, mgrid);
        mma_gemm<<<g, 256>>>(x, 128, 8, Bp, Y, 256, N, nullptr, 0);
    }

    // graph build
    deg_cnt_kernel<<<eblk, 256>>>(ei, E);
    scan1_kernel<<<nb1024, 1024>>>(N);
    scan2_kernel<<<1, 256>>>(nb1024);
    scan3_kernel<<<nb1024, 1024>>>(N);
    fill_kernel<<<eblk, 256>>>(ei, E);

    // ---- layer 1 (output-space propagation):
    // out1 = relu( x(W0-W2) + L(xW1 + 2 L(xW2)) + b1 )
    // Y layout (stride 256): [y1 | y2 | y0 | pad]
    prop_kernel<64><<<pblk, 256>>>(Y + 64, 256, U, 64, Y, 256, 2.f, 1.f, nullptr, 0, N);
    prop_kernel<64><<<pblk, 256>>>(U, 64, H2, 192, Y + 128, 256, 1.f, 1.f, b1, 1, N);

    // ---- layer 2 ----
    prop_kernel<64><<<pblk, 256>>>(H2, 192, H2 + 64, 192, nullptr, 0, 1.f, 0.f, nullptr, 0, N);
    prop_kernel<64><<<pblk, 256>>>(H2 + 64, 192, H2 + 128, 192, H2, 192, 2.f, -1.f, nullptr, 0, N);
    {
        dim3 g(1, mgrid);
        mma_gemm<<<g, 256>>>(H2, 192, 12, Bp + 8192, H3, 384, N, b2, 1);
    }

    // ---- layer 3 ----
    prop_kernel<128><<<pblk, 256>>>(H3, 384, H3 + 128, 384, nullptr, 0, 1.f, 0.f, nullptr, 0, N);
    prop_kernel<128><<<pblk, 256>>>(H3 + 128, 384, H3 + 256, 384, H3, 384, 2.f, -1.f, nullptr, 0, N);
    {
        dim3 g(2, mgrid);
        mma_gemm<<<g, 256>>>(H3, 384, 24, Bp + 14336, (float*)d_out, 256, N, b3, 0);
    }
}